// round 3
// baseline (speedup 1.0000x reference)
#include <cuda_runtime.h>

#define NE 8
#define NT 2048
#define ND 2048
#define NH 4096

// Scratch for the SwiGLU intermediate h = silu(x@w1) * (x@w3): E*T*H fp32 = 256 MiB.
// __device__ global (no allocation in kernel_launch, per harness rules).
__device__ float g_h[(long long)NE * NT * NH];

// ---------------------------------------------------------------------------
// GEMM1 (fused): for expert e:  g_h[t,h] = silu(x@w1)[t,h] * (x@w3)[t,h]
// Tiles: BM=128, BN=64, BK=16. 256 threads, each computes 8x4 for BOTH B1 and B3
// accumulators (A tile shared between the two GEMMs).
// ---------------------------------------------------------------------------
__global__ __launch_bounds__(256, 2)
void gemm1_swiglu(const float* __restrict__ X,
                  const float* __restrict__ W1,
                  const float* __restrict__ W3)
{
    constexpr int BM = 128, BN = 64, BK = 16;
    __shared__ float As [BK][BM];   // A stored transposed: As[k][m]
    __shared__ float B1s[BK][BN];
    __shared__ float B3s[BK][BN];

    const int e = blockIdx.z;
    const float* A  = X  + (long long)e * NT * ND;
    const float* B1 = W1 + (long long)e * ND * NH;
    const float* B3 = W3 + (long long)e * ND * NH;
    float* C = g_h + (long long)e * NT * NH;

    const int row0 = blockIdx.y * BM;   // token rows
    const int col0 = blockIdx.x * BN;   // hidden cols
    const int tid  = threadIdx.x;

    // compute mapping: ty -> 8 rows, tx -> 4 cols
    const int ty = tid >> 4;            // 0..15
    const int tx = tid & 15;            // 0..15

    // A-load mapping: 128x16 tile = 512 float4; 2 per thread
    const int aRow = tid >> 2;          // 0..63  (and +64)
    const int aCol = (tid & 3) << 2;    // 0,4,8,12
    // B-load mapping: 16x64 tile = 256 float4; 1 per thread (per matrix)
    const int bRow = tid >> 4;          // 0..15
    const int bCol = (tid & 15) << 2;   // 0..60

    float acc1[8][4];
    float acc3[8][4];
    #pragma unroll
    for (int i = 0; i < 8; ++i)
        #pragma unroll
        for (int j = 0; j < 4; ++j) { acc1[i][j] = 0.f; acc3[i][j] = 0.f; }

    for (int k0 = 0; k0 < ND; k0 += BK) {
        // --- load A tile (transposed into SMEM) ---
        #pragma unroll
        for (int r = 0; r < 2; ++r) {
            const int row = aRow + r * 64;
            float4 v = *(const float4*)&A[(long long)(row0 + row) * ND + k0 + aCol];
            As[aCol + 0][row] = v.x;
            As[aCol + 1][row] = v.y;
            As[aCol + 2][row] = v.z;
            As[aCol + 3][row] = v.w;
        }
        // --- load B1/B3 tiles ---
        {
            float4 v1 = *(const float4*)&B1[(long long)(k0 + bRow) * NH + col0 + bCol];
            *(float4*)&B1s[bRow][bCol] = v1;
            float4 v3 = *(const float4*)&B3[(long long)(k0 + bRow) * NH + col0 + bCol];
            *(float4*)&B3s[bRow][bCol] = v3;
        }
        __syncthreads();

        #pragma unroll
        for (int kk = 0; kk < BK; ++kk) {
            float a[8];
            #pragma unroll
            for (int i = 0; i < 8; ++i) a[i] = As[kk][ty * 8 + i];
            const float4 b1 = *(const float4*)&B1s[kk][tx * 4];
            const float4 b3 = *(const float4*)&B3s[kk][tx * 4];
            #pragma unroll
            for (int i = 0; i < 8; ++i) {
                acc1[i][0] += a[i] * b1.x;
                acc1[i][1] += a[i] * b1.y;
                acc1[i][2] += a[i] * b1.z;
                acc1[i][3] += a[i] * b1.w;
                acc3[i][0] += a[i] * b3.x;
                acc3[i][1] += a[i] * b3.y;
                acc3[i][2] += a[i] * b3.z;
                acc3[i][3] += a[i] * b3.w;
            }
        }
        __syncthreads();
    }

    // --- epilogue: silu(v1) * v3, vectorized store ---
    #pragma unroll
    for (int i = 0; i < 8; ++i) {
        float4 o;
        float* po = (float*)&o;
        #pragma unroll
        for (int j = 0; j < 4; ++j) {
            const float v1 = acc1[i][j];
            const float v3 = acc3[i][j];
            const float s  = v1 / (1.0f + __expf(-v1));  // silu
            po[j] = s * v3;
        }
        *(float4*)&C[(long long)(row0 + ty * 8 + i) * NH + col0 + tx * 4] = o;
    }
}

// ---------------------------------------------------------------------------
// GEMM2: out[t,d] = h @ w2.  Tiles: BM=128, BN=128, BK=16. 256 threads, 8x8
// microtile (cols split as tx*4 and 64+tx*4 for conflict-free SMEM reads).
// ---------------------------------------------------------------------------
__global__ __launch_bounds__(256, 2)
void gemm2_kernel(const float* __restrict__ W2, float* __restrict__ Out)
{
    constexpr int BM = 128, BN = 128, BK = 16;
    __shared__ float As[BK][BM];
    __shared__ float Bs[BK][BN];

    const int e = blockIdx.z;
    const float* A = g_h + (long long)e * NT * NH;
    const float* B = W2  + (long long)e * NH * ND;
    float* C = Out + (long long)e * NT * ND;

    const int row0 = blockIdx.y * BM;
    const int col0 = blockIdx.x * BN;
    const int tid  = threadIdx.x;

    const int ty = tid >> 4;            // 0..15 -> 8 rows
    const int tx = tid & 15;            // 0..15 -> cols tx*4 and 64+tx*4

    const int aRow = tid >> 2;          // 0..63 (and +64)
    const int aCol = (tid & 3) << 2;
    const int bRow = tid >> 5;          // 0..7 (and +8)
    const int bCol = (tid & 31) << 2;   // 0..124

    float acc[8][8];
    #pragma unroll
    for (int i = 0; i < 8; ++i)
        #pragma unroll
        for (int j = 0; j < 8; ++j) acc[i][j] = 0.f;

    for (int k0 = 0; k0 < NH; k0 += BK) {
        #pragma unroll
        for (int r = 0; r < 2; ++r) {
            const int row = aRow + r * 64;
            float4 v = *(const float4*)&A[(long long)(row0 + row) * NH + k0 + aCol];
            As[aCol + 0][row] = v.x;
            As[aCol + 1][row] = v.y;
            As[aCol + 2][row] = v.z;
            As[aCol + 3][row] = v.w;
        }
        #pragma unroll
        for (int r = 0; r < 2; ++r) {
            const int row = bRow + r * 8;
            float4 v = *(const float4*)&B[(long long)(k0 + row) * ND + col0 + bCol];
            *(float4*)&Bs[row][bCol] = v;
        }
        __syncthreads();

        #pragma unroll
        for (int kk = 0; kk < BK; ++kk) {
            float a[8];
            #pragma unroll
            for (int i = 0; i < 8; ++i) a[i] = As[kk][ty * 8 + i];
            const float4 bl = *(const float4*)&Bs[kk][tx * 4];
            const float4 bh = *(const float4*)&Bs[kk][64 + tx * 4];
            #pragma unroll
            for (int i = 0; i < 8; ++i) {
                acc[i][0] += a[i] * bl.x;
                acc[i][1] += a[i] * bl.y;
                acc[i][2] += a[i] * bl.z;
                acc[i][3] += a[i] * bl.w;
                acc[i][4] += a[i] * bh.x;
                acc[i][5] += a[i] * bh.y;
                acc[i][6] += a[i] * bh.z;
                acc[i][7] += a[i] * bh.w;
            }
        }
        __syncthreads();
    }

    #pragma unroll
    for (int i = 0; i < 8; ++i) {
        float4 o0, o1;
        o0.x = acc[i][0]; o0.y = acc[i][1]; o0.z = acc[i][2]; o0.w = acc[i][3];
        o1.x = acc[i][4]; o1.y = acc[i][5]; o1.z = acc[i][6]; o1.w = acc[i][7];
        const long long rbase = (long long)(row0 + ty * 8 + i) * ND + col0;
        *(float4*)&C[rbase + tx * 4]      = o0;
        *(float4*)&C[rbase + 64 + tx * 4] = o1;
    }
}

// ---------------------------------------------------------------------------
// Inputs (metadata order): x [E,T,D] fp32, w1 [E,D,H] fp32, w2 [E,H,D] fp32,
// w3 [E,D,H] fp32. Output: [E,T,D] fp32.
// ---------------------------------------------------------------------------
extern "C" void kernel_launch(void* const* d_in, const int* in_sizes, int n_in,
                              void* d_out, int out_size)
{
    const float* x  = (const float*)d_in[0];
    const float* w1 = (const float*)d_in[1];
    const float* w2 = (const float*)d_in[2];
    const float* w3 = (const float*)d_in[3];
    float* out = (float*)d_out;

    dim3 g1(NH / 64, NT / 128, NE);     // 64 x 16 x 8
    gemm1_swiglu<<<g1, 256>>>(x, w1, w3);

    dim3 g2(ND / 128, NT / 128, NE);    // 16 x 16 x 8
    gemm2_kernel<<<g2, 256>>>(w2, out);
}

// round 5
// speedup vs baseline: 2.7383x; 2.7383x over previous
#include <cuda_runtime.h>
#include <cuda_fp16.h>
#include <cstdint>

#define NE 8
#define NT 2048
#define ND 2048
#define NH 4096

// ---------------- scratch (static __device__, allocation-free) ----------------
__device__ __half g_xh [(long long)NE * NT * ND];
__device__ __half g_xl [(long long)NE * NT * ND];
__device__ __half g_w1h[(long long)NE * ND * NH];
__device__ __half g_w1l[(long long)NE * ND * NH];
__device__ __half g_w3h[(long long)NE * ND * NH];
__device__ __half g_w3l[(long long)NE * ND * NH];
__device__ __half g_w2h[(long long)NE * NH * ND];
__device__ __half g_w2l[(long long)NE * NH * ND];
__device__ float  g_t1 [(long long)NE * NT * NH];
__device__ __half g_hh [(long long)NE * NT * NH];
__device__ __half g_hl [(long long)NE * NT * NH];

// ---------------- PTX helpers (all base-target sm_80+ instructions) ----------------
__device__ __forceinline__ void cp16s(uint32_t dst, const void* src) {
    asm volatile("cp.async.cg.shared.global [%0], [%1], 16;" :: "r"(dst), "l"(src));
}
__device__ __forceinline__ void ldsm4(uint32_t* r, uint32_t a) {
    asm volatile("ldmatrix.sync.aligned.m8n8.x4.shared.b16 {%0,%1,%2,%3}, [%4];"
                 : "=r"(r[0]), "=r"(r[1]), "=r"(r[2]), "=r"(r[3]) : "r"(a));
}
__device__ __forceinline__ void ldsm2t(uint32_t* r, uint32_t a) {
    asm volatile("ldmatrix.sync.aligned.m8n8.x2.trans.shared.b16 {%0,%1}, [%2];"
                 : "=r"(r[0]), "=r"(r[1]) : "r"(a));
}
__device__ __forceinline__ void mma16816(float* d, const uint32_t* a, const uint32_t* b) {
    asm volatile(
        "mma.sync.aligned.m16n8k16.row.col.f32.f16.f16.f32 "
        "{%0,%1,%2,%3}, {%4,%5,%6,%7}, {%8,%9}, {%0,%1,%2,%3};"
        : "+f"(d[0]), "+f"(d[1]), "+f"(d[2]), "+f"(d[3])
        : "r"(a[0]), "r"(a[1]), "r"(a[2]), "r"(a[3]), "r"(b[0]), "r"(b[1]));
}

// ---------------- conversion: fp32 -> fp16 hi + fp16 lo (elementwise) ----------------
__global__ void conv_split(const float4* __restrict__ in,
                           __half2* __restrict__ oh, __half2* __restrict__ ol) {
    long long i = (long long)blockIdx.x * blockDim.x + threadIdx.x;
    float4 v = in[i];
    __half2 h0 = __floats2half2_rn(v.x, v.y);
    __half2 h1 = __floats2half2_rn(v.z, v.w);
    float2 f0 = __half22float2(h0);
    float2 f1 = __half22float2(h1);
    __half2 l0 = __floats2half2_rn(v.x - f0.x, v.y - f0.y);
    __half2 l1 = __floats2half2_rn(v.z - f1.x, v.w - f1.y);
    __half2 hv[2] = {h0, h1};
    __half2 lv[2] = {l0, l1};
    *(uint2*)(oh + 2 * i) = *(uint2*)hv;
    *(uint2*)(ol + 2 * i) = *(uint2*)lv;
}

// ---------------- GEMM: C[M,N] = A[M,K] @ B[K,N], 3-term fp16 split ----------------
// BM=BN=128, BK=64, 8 warps (2m x 4n), warp tile 64x32.
// SMEM stage = Ah(16K) | Al(16K) | Bh(16K) | Bl(16K) = 64KB; 3 stages = 192KB.
// A swizzle: off = row*128 + ((kchunk ^ (row&7))<<4)      (row = m, 8 k-chunks of 16B)
// B swizzle: off = krow*256 + ((nchunk ^ (krow&7))<<4)    (16 n-chunks of 16B)
// EPI 0: store fp32 C.  EPI 1: v = silu(T1)*acc -> fp16 hi/lo (Hh,Hl).
template<int KFULL, int NN, int EPI>
__global__ __launch_bounds__(256, 1)
void gemm_mma(const __half* __restrict__ Ah, const __half* __restrict__ Al,
              const __half* __restrict__ Bh, const __half* __restrict__ Bl,
              float* __restrict__ C,
              const float* __restrict__ T1,
              __half* __restrict__ Hh, __half* __restrict__ Hl)
{
    extern __shared__ __align__(128) char smem[];
    const uint32_t sbase = (uint32_t)__cvta_generic_to_shared(smem);
    const int tid = threadIdx.x;
    const int e  = blockIdx.z;
    const int n0 = blockIdx.x * 128;
    const int m0 = blockIdx.y * 128;

    const __half* pAh = Ah + (long long)e * NT * KFULL + (long long)m0 * KFULL;
    const __half* pAl = Al + (long long)e * NT * KFULL + (long long)m0 * KFULL;
    const __half* pBh = Bh + (long long)e * KFULL * NN + n0;
    const __half* pBl = Bl + (long long)e * KFULL * NN + n0;

    const int warp = tid >> 5, lane = tid & 31;
    const int wm = (warp & 1) * 64;      // warp row offset within CTA tile
    const int wn = (warp >> 1) * 32;     // warp col offset

    float acc[4][4][4];
    #pragma unroll
    for (int i = 0; i < 4; i++)
        #pragma unroll
        for (int j = 0; j < 4; j++)
            #pragma unroll
            for (int r = 0; r < 4; r++) acc[i][j][r] = 0.f;

    auto load_stage = [&](int slot, int k0) {
        const uint32_t sb = sbase + slot * 65536;
        #pragma unroll
        for (int i = 0; i < 4; i++) {          // A: 128 rows x 8 chunks (per matrix)
            int id = tid + i * 256;
            int row = id >> 3, c = id & 7;
            long long go = (long long)row * KFULL + k0 + c * 8;
            uint32_t so = sb + row * 128 + ((c ^ (row & 7)) << 4);
            cp16s(so,         pAh + go);
            cp16s(so + 16384, pAl + go);
        }
        #pragma unroll
        for (int i = 0; i < 4; i++) {          // B: 64 rows x 16 chunks (per matrix)
            int id = tid + i * 256;
            int row = id >> 4, c = id & 15;
            long long go = (long long)(k0 + row) * NN + c * 8;
            uint32_t so = sb + 32768 + row * 256 + ((c ^ (row & 7)) << 4);
            cp16s(so,         pBh + go);
            cp16s(so + 16384, pBl + go);
        }
        asm volatile("cp.async.commit_group;" ::: "memory");
    };

    load_stage(0, 0);
    load_stage(1, 64);
    load_stage(2, 128);

    const int NKC = KFULL / 64;
    for (int ch = 0; ch < NKC; ch++) {
        asm volatile("cp.async.wait_group 2;" ::: "memory");
        __syncthreads();
        const uint32_t sb = sbase + (ch % 3) * 65536;

        #pragma unroll
        for (int ks = 0; ks < 4; ks++) {       // 4 x k16 steps within BK=64
            uint32_t aH[4][4], aL[4][4], bH[4][2], bL[4][2];
            #pragma unroll
            for (int mt = 0; mt < 4; mt++) {
                int row = wm + mt * 16 + (lane & 15);
                int cc  = ks * 2 + (lane >> 4);
                uint32_t ad = sb + row * 128 + ((cc ^ (row & 7)) << 4);
                ldsm4(aH[mt], ad);
                ldsm4(aL[mt], ad + 16384);
            }
            #pragma unroll
            for (int nt = 0; nt < 4; nt++) {
                int kr = ks * 16 + (lane & 15);
                int nc = (wn >> 3) + nt;
                uint32_t bd = sb + 32768 + kr * 256 + ((nc ^ (kr & 7)) << 4);
                ldsm2t(bH[nt], bd);
                ldsm2t(bL[nt], bd + 16384);
            }
            #pragma unroll
            for (int mt = 0; mt < 4; mt++)
                #pragma unroll
                for (int nt = 0; nt < 4; nt++) {
                    mma16816(acc[mt][nt], aH[mt], bH[nt]);
                    mma16816(acc[mt][nt], aH[mt], bL[nt]);
                    mma16816(acc[mt][nt], aL[mt], bH[nt]);
                }
        }
        __syncthreads();
        if (ch + 3 < NKC) load_stage(ch % 3, (ch + 3) * 64);
        else asm volatile("cp.async.commit_group;" ::: "memory");
    }

    // ---------------- epilogue ----------------
    #pragma unroll
    for (int mt = 0; mt < 4; mt++)
        #pragma unroll
        for (int nt = 0; nt < 4; nt++) {
            const int row = m0 + wm + mt * 16 + (lane >> 2);
            const int col = n0 + wn + nt * 8 + (lane & 3) * 2;
            const long long i0 = ((long long)e * NT + row) * NN + col;
            const long long i1 = i0 + 8LL * NN;
            if (EPI == 0) {
                *(float2*)&C[i0] = make_float2(acc[mt][nt][0], acc[mt][nt][1]);
                *(float2*)&C[i1] = make_float2(acc[mt][nt][2], acc[mt][nt][3]);
            } else {
                const float2 ta = *(const float2*)&T1[i0];
                const float2 tb = *(const float2*)&T1[i1];
                const float v0 = acc[mt][nt][0] * ta.x / (1.f + __expf(-ta.x));
                const float v1 = acc[mt][nt][1] * ta.y / (1.f + __expf(-ta.y));
                const float v2 = acc[mt][nt][2] * tb.x / (1.f + __expf(-tb.x));
                const float v3 = acc[mt][nt][3] * tb.y / (1.f + __expf(-tb.y));
                __half2 h0 = __floats2half2_rn(v0, v1);
                float2  f0 = __half22float2(h0);
                __half2 l0 = __floats2half2_rn(v0 - f0.x, v1 - f0.y);
                __half2 h1 = __floats2half2_rn(v2, v3);
                float2  f1 = __half22float2(h1);
                __half2 l1 = __floats2half2_rn(v2 - f1.x, v3 - f1.y);
                *(__half2*)&Hh[i0] = h0;
                *(__half2*)&Hl[i0] = l0;
                *(__half2*)&Hh[i1] = h1;
                *(__half2*)&Hl[i1] = l1;
            }
        }
}

// ---------------- launch ----------------
// Inputs (metadata order): x [E,T,D] fp32, w1 [E,D,H], w2 [E,H,D], w3 [E,D,H].
// Output: [E,T,D] fp32.
extern "C" void kernel_launch(void* const* d_in, const int* in_sizes, int n_in,
                              void* d_out, int out_size)
{
    const float* x  = (const float*)d_in[0];
    const float* w1 = (const float*)d_in[1];
    const float* w2 = (const float*)d_in[2];
    const float* w3 = (const float*)d_in[3];
    float* out = (float*)d_out;

    const int SMEM = 196608;
    cudaFuncSetAttribute(gemm_mma<ND, NH, 0>, cudaFuncAttributeMaxDynamicSharedMemorySize, SMEM);
    cudaFuncSetAttribute(gemm_mma<ND, NH, 1>, cudaFuncAttributeMaxDynamicSharedMemorySize, SMEM);
    cudaFuncSetAttribute(gemm_mma<NH, ND, 0>, cudaFuncAttributeMaxDynamicSharedMemorySize, SMEM);

    void *xh, *xl, *w1h, *w1l, *w3h, *w3l, *w2h, *w2l, *t1, *hh, *hl;
    cudaGetSymbolAddress(&xh,  g_xh);  cudaGetSymbolAddress(&xl,  g_xl);
    cudaGetSymbolAddress(&w1h, g_w1h); cudaGetSymbolAddress(&w1l, g_w1l);
    cudaGetSymbolAddress(&w3h, g_w3h); cudaGetSymbolAddress(&w3l, g_w3l);
    cudaGetSymbolAddress(&w2h, g_w2h); cudaGetSymbolAddress(&w2l, g_w2l);
    cudaGetSymbolAddress(&t1,  g_t1);
    cudaGetSymbolAddress(&hh,  g_hh);  cudaGetSymbolAddress(&hl,  g_hl);

    // conversions (fp32 -> fp16 hi/lo)
    const long long nx = (long long)NE * NT * ND;   // 33.5M
    const long long nw = (long long)NE * ND * NH;   // 67M
    conv_split<<<(int)(nx / 4 / 256), 256>>>((const float4*)x,  (__half2*)xh,  (__half2*)xl);
    conv_split<<<(int)(nw / 4 / 256), 256>>>((const float4*)w1, (__half2*)w1h, (__half2*)w1l);
    conv_split<<<(int)(nw / 4 / 256), 256>>>((const float4*)w3, (__half2*)w3h, (__half2*)w3l);
    conv_split<<<(int)(nw / 4 / 256), 256>>>((const float4*)w2, (__half2*)w2h, (__half2*)w2l);

    // t1 = x @ w1
    gemm_mma<ND, NH, 0><<<dim3(NH / 128, NT / 128, NE), 256, SMEM>>>(
        (const __half*)xh, (const __half*)xl, (const __half*)w1h, (const __half*)w1l,
        (float*)t1, nullptr, nullptr, nullptr);

    // h = silu(t1) * (x @ w3)   (fp16 hi/lo)
    gemm_mma<ND, NH, 1><<<dim3(NH / 128, NT / 128, NE), 256, SMEM>>>(
        (const __half*)xh, (const __half*)xl, (const __half*)w3h, (const __half*)w3l,
        nullptr, (const float*)t1, (__half*)hh, (__half*)hl);

    // out = h @ w2
    gemm_mma<NH, ND, 0><<<dim3(ND / 128, NT / 128, NE), 256, SMEM>>>(
        (const __half*)hh, (const __half*)hl, (const __half*)w2h, (const __half*)w2l,
        out, nullptr, nullptr, nullptr);
}

// round 6
// speedup vs baseline: 7.0608x; 2.5785x over previous
#include <cuda_runtime.h>
#include <cuda_fp16.h>
#include <cstdint>

#define NE 8
#define NT 2048
#define ND 2048
#define NH 4096

// ---------------- scratch (static __device__, allocation-free) ----------------
__device__ __half g_x16[(long long)NE * NT * ND];
__device__ __half g_w1 [(long long)NE * ND * NH];
__device__ __half g_w3 [(long long)NE * ND * NH];
__device__ __half g_w2 [(long long)NE * NH * ND];
__device__ __half g_h16[(long long)NE * NT * NH];

// ---------------- PTX helpers (base-target sm_80+) ----------------
__device__ __forceinline__ void cp16s(uint32_t dst, const void* src) {
    asm volatile("cp.async.cg.shared.global [%0], [%1], 16;" :: "r"(dst), "l"(src));
}
__device__ __forceinline__ void ldsm4(uint32_t* r, uint32_t a) {
    asm volatile("ldmatrix.sync.aligned.m8n8.x4.shared.b16 {%0,%1,%2,%3}, [%4];"
                 : "=r"(r[0]), "=r"(r[1]), "=r"(r[2]), "=r"(r[3]) : "r"(a));
}
__device__ __forceinline__ void ldsm2t(uint32_t* r, uint32_t a) {
    asm volatile("ldmatrix.sync.aligned.m8n8.x2.trans.shared.b16 {%0,%1}, [%2];"
                 : "=r"(r[0]), "=r"(r[1]) : "r"(a));
}
__device__ __forceinline__ void mma16816(float* d, const uint32_t* a, const uint32_t* b) {
    asm volatile(
        "mma.sync.aligned.m16n8k16.row.col.f32.f16.f16.f32 "
        "{%0,%1,%2,%3}, {%4,%5,%6,%7}, {%8,%9}, {%0,%1,%2,%3};"
        : "+f"(d[0]), "+f"(d[1]), "+f"(d[2]), "+f"(d[3])
        : "r"(a[0]), "r"(a[1]), "r"(a[2]), "r"(a[3]), "r"(b[0]), "r"(b[1]));
}

// ---------------- conversion: fp32 -> fp16 (elementwise, 8/thread) ----------------
__global__ void conv_h16(const float4* __restrict__ in, __half2* __restrict__ o) {
    long long i = (long long)blockIdx.x * blockDim.x + threadIdx.x;
    float4 v0 = in[2 * i];
    float4 v1 = in[2 * i + 1];
    __half2 h[4];
    h[0] = __floats2half2_rn(v0.x, v0.y);
    h[1] = __floats2half2_rn(v0.z, v0.w);
    h[2] = __floats2half2_rn(v1.x, v1.y);
    h[3] = __floats2half2_rn(v1.z, v1.w);
    *(uint4*)(o + 4 * i) = *(uint4*)h;
}

// ---------------- GEMM13 (fused): h = silu(x@w1) * (x@w3) ----------------
// BM=128, BN=128 (same cols for w1 & w3), BK=64, 8 warps (2m x 4n), warp 64x32.
// SMEM stage = A(16K) | B1(16K) | B3(16K) = 48KB; 4 stages = 192KB.
__global__ __launch_bounds__(256, 1)
void gemm13_fused(const __half* __restrict__ X, const __half* __restrict__ W1,
                  const __half* __restrict__ W3, __half* __restrict__ H)
{
    extern __shared__ __align__(128) char smem[];
    const uint32_t sbase = (uint32_t)__cvta_generic_to_shared(smem);
    const int tid = threadIdx.x;
    const int e  = blockIdx.z;
    const int n0 = blockIdx.x * 128;
    const int m0 = blockIdx.y * 128;

    const __half* pA  = X  + (long long)e * NT * ND + (long long)m0 * ND;
    const __half* pB1 = W1 + (long long)e * ND * NH + n0;
    const __half* pB3 = W3 + (long long)e * ND * NH + n0;

    const int warp = tid >> 5, lane = tid & 31;
    const int wm = (warp & 1) * 64;
    const int wn = (warp >> 1) * 32;

    float acc1[4][4][4], acc3[4][4][4];
    #pragma unroll
    for (int i = 0; i < 4; i++)
        #pragma unroll
        for (int j = 0; j < 4; j++)
            #pragma unroll
            for (int r = 0; r < 4; r++) { acc1[i][j][r] = 0.f; acc3[i][j][r] = 0.f; }

    auto load_stage = [&](int slot, int k0) {
        const uint32_t sb = sbase + slot * 49152;
        #pragma unroll
        for (int i = 0; i < 4; i++) {          // A: 128 rows x 8 chunks of 16B
            int id = tid + i * 256;
            int row = id >> 3, c = id & 7;
            cp16s(sb + row * 128 + ((c ^ (row & 7)) << 4),
                  pA + (long long)row * ND + k0 + c * 8);
        }
        #pragma unroll
        for (int i = 0; i < 4; i++) {          // B1/B3: 64 rows x 16 chunks
            int id = tid + i * 256;
            int row = id >> 4, c = id & 15;
            long long go = (long long)(k0 + row) * NH + c * 8;
            uint32_t so = sb + 16384 + row * 256 + ((c ^ (row & 7)) << 4);
            cp16s(so,         pB1 + go);
            cp16s(so + 16384, pB3 + go);
        }
        asm volatile("cp.async.commit_group;" ::: "memory");
    };

    load_stage(0, 0);
    load_stage(1, 64);
    load_stage(2, 128);
    load_stage(3, 192);

    const int NKC = ND / 64;
    for (int ch = 0; ch < NKC; ch++) {
        asm volatile("cp.async.wait_group 3;" ::: "memory");
        __syncthreads();
        const uint32_t sb = sbase + (ch & 3) * 49152;

        #pragma unroll
        for (int ks = 0; ks < 4; ks++) {
            uint32_t av[4][4], b1[4][2], b3[4][2];
            #pragma unroll
            for (int mt = 0; mt < 4; mt++) {
                int row = wm + mt * 16 + (lane & 15);
                int cc  = ks * 2 + (lane >> 4);
                ldsm4(av[mt], sb + row * 128 + ((cc ^ (row & 7)) << 4));
            }
            #pragma unroll
            for (int nt = 0; nt < 4; nt++) {
                int kr = ks * 16 + (lane & 15);
                int nc = (wn >> 3) + nt;
                uint32_t bd = sb + 16384 + kr * 256 + ((nc ^ (kr & 7)) << 4);
                ldsm2t(b1[nt], bd);
                ldsm2t(b3[nt], bd + 16384);
            }
            #pragma unroll
            for (int mt = 0; mt < 4; mt++)
                #pragma unroll
                for (int nt = 0; nt < 4; nt++) {
                    mma16816(acc1[mt][nt], av[mt], b1[nt]);
                    mma16816(acc3[mt][nt], av[mt], b3[nt]);
                }
        }
        __syncthreads();
        if (ch + 4 < NKC) load_stage(ch & 3, (ch + 4) * 64);
        else asm volatile("cp.async.commit_group;" ::: "memory");
    }

    // epilogue: h = silu(acc1) * acc3 -> fp16
    #pragma unroll
    for (int mt = 0; mt < 4; mt++)
        #pragma unroll
        for (int nt = 0; nt < 4; nt++) {
            const int row = m0 + wm + mt * 16 + (lane >> 2);
            const int col = n0 + wn + nt * 8 + (lane & 3) * 2;
            const long long i0 = ((long long)e * NT + row) * NH + col;
            const long long i1 = i0 + 8LL * NH;
            const float a0 = acc1[mt][nt][0], a1 = acc1[mt][nt][1];
            const float a2 = acc1[mt][nt][2], a3 = acc1[mt][nt][3];
            const float v0 = acc3[mt][nt][0] * a0 / (1.f + __expf(-a0));
            const float v1 = acc3[mt][nt][1] * a1 / (1.f + __expf(-a1));
            const float v2 = acc3[mt][nt][2] * a2 / (1.f + __expf(-a2));
            const float v3 = acc3[mt][nt][3] * a3 / (1.f + __expf(-a3));
            *(__half2*)&H[i0] = __floats2half2_rn(v0, v1);
            *(__half2*)&H[i1] = __floats2half2_rn(v2, v3);
        }
}

// ---------------- GEMM2: out = h @ w2 (fp32 out) ----------------
// BM=128, BN=128, BK=64; SMEM stage = A(16K) | B(16K) = 32KB; 4 stages = 128KB.
__global__ __launch_bounds__(256, 1)
void gemm2_out(const __half* __restrict__ Hm, const __half* __restrict__ W2,
               float* __restrict__ Out)
{
    extern __shared__ __align__(128) char smem[];
    const uint32_t sbase = (uint32_t)__cvta_generic_to_shared(smem);
    const int tid = threadIdx.x;
    const int e  = blockIdx.z;
    const int n0 = blockIdx.x * 128;
    const int m0 = blockIdx.y * 128;

    const __half* pA = Hm + (long long)e * NT * NH + (long long)m0 * NH;
    const __half* pB = W2 + (long long)e * NH * ND + n0;

    const int warp = tid >> 5, lane = tid & 31;
    const int wm = (warp & 1) * 64;
    const int wn = (warp >> 1) * 32;

    float acc[4][4][4];
    #pragma unroll
    for (int i = 0; i < 4; i++)
        #pragma unroll
        for (int j = 0; j < 4; j++)
            #pragma unroll
            for (int r = 0; r < 4; r++) acc[i][j][r] = 0.f;

    auto load_stage = [&](int slot, int k0) {
        const uint32_t sb = sbase + slot * 32768;
        #pragma unroll
        for (int i = 0; i < 4; i++) {
            int id = tid + i * 256;
            int row = id >> 3, c = id & 7;
            cp16s(sb + row * 128 + ((c ^ (row & 7)) << 4),
                  pA + (long long)row * NH + k0 + c * 8);
        }
        #pragma unroll
        for (int i = 0; i < 4; i++) {
            int id = tid + i * 256;
            int row = id >> 4, c = id & 15;
            cp16s(sb + 16384 + row * 256 + ((c ^ (row & 7)) << 4),
                  pB + (long long)(k0 + row) * ND + c * 8);
        }
        asm volatile("cp.async.commit_group;" ::: "memory");
    };

    load_stage(0, 0);
    load_stage(1, 64);
    load_stage(2, 128);
    load_stage(3, 192);

    const int NKC = NH / 64;
    for (int ch = 0; ch < NKC; ch++) {
        asm volatile("cp.async.wait_group 3;" ::: "memory");
        __syncthreads();
        const uint32_t sb = sbase + (ch & 3) * 32768;

        #pragma unroll
        for (int ks = 0; ks < 4; ks++) {
            uint32_t av[4][4], bv[4][2];
            #pragma unroll
            for (int mt = 0; mt < 4; mt++) {
                int row = wm + mt * 16 + (lane & 15);
                int cc  = ks * 2 + (lane >> 4);
                ldsm4(av[mt], sb + row * 128 + ((cc ^ (row & 7)) << 4));
            }
            #pragma unroll
            for (int nt = 0; nt < 4; nt++) {
                int kr = ks * 16 + (lane & 15);
                int nc = (wn >> 3) + nt;
                ldsm2t(bv[nt], sb + 16384 + kr * 256 + ((nc ^ (kr & 7)) << 4));
            }
            #pragma unroll
            for (int mt = 0; mt < 4; mt++)
                #pragma unroll
                for (int nt = 0; nt < 4; nt++)
                    mma16816(acc[mt][nt], av[mt], bv[nt]);
        }
        __syncthreads();
        if (ch + 4 < NKC) load_stage(ch & 3, (ch + 4) * 64);
        else asm volatile("cp.async.commit_group;" ::: "memory");
    }

    #pragma unroll
    for (int mt = 0; mt < 4; mt++)
        #pragma unroll
        for (int nt = 0; nt < 4; nt++) {
            const int row = m0 + wm + mt * 16 + (lane >> 2);
            const int col = n0 + wn + nt * 8 + (lane & 3) * 2;
            const long long i0 = ((long long)e * NT + row) * ND + col;
            const long long i1 = i0 + 8LL * ND;
            *(float2*)&Out[i0] = make_float2(acc[mt][nt][0], acc[mt][nt][1]);
            *(float2*)&Out[i1] = make_float2(acc[mt][nt][2], acc[mt][nt][3]);
        }
}

// ---------------- launch ----------------
// Inputs: x [E,T,D] fp32, w1 [E,D,H], w2 [E,H,D], w3 [E,D,H]. Output [E,T,D] fp32.
extern "C" void kernel_launch(void* const* d_in, const int* in_sizes, int n_in,
                              void* d_out, int out_size)
{
    const float* x  = (const float*)d_in[0];
    const float* w1 = (const float*)d_in[1];
    const float* w2 = (const float*)d_in[2];
    const float* w3 = (const float*)d_in[3];
    float* out = (float*)d_out;

    cudaFuncSetAttribute(gemm13_fused, cudaFuncAttributeMaxDynamicSharedMemorySize, 196608);
    cudaFuncSetAttribute(gemm2_out,    cudaFuncAttributeMaxDynamicSharedMemorySize, 131072);

    void *x16, *w1p, *w3p, *w2p, *h16;
    cudaGetSymbolAddress(&x16, g_x16);
    cudaGetSymbolAddress(&w1p, g_w1);
    cudaGetSymbolAddress(&w3p, g_w3);
    cudaGetSymbolAddress(&w2p, g_w2);
    cudaGetSymbolAddress(&h16, g_h16);

    const long long nx = (long long)NE * NT * ND;
    const long long nw = (long long)NE * ND * NH;
    conv_h16<<<(int)(nx / 8 / 256), 256>>>((const float4*)x,  (__half2*)x16);
    conv_h16<<<(int)(nw / 8 / 256), 256>>>((const float4*)w1, (__half2*)w1p);
    conv_h16<<<(int)(nw / 8 / 256), 256>>>((const float4*)w3, (__half2*)w3p);
    conv_h16<<<(int)(nw / 8 / 256), 256>>>((const float4*)w2, (__half2*)w2p);

    gemm13_fused<<<dim3(NH / 128, NT / 128, NE), 256, 196608>>>(
        (const __half*)x16, (const __half*)w1p, (const __half*)w3p, (__half*)h16);

    gemm2_out<<<dim3(ND / 128, NT / 128, NE), 256, 131072>>>(
        (const __half*)h16, (const __half*)w2p, out);
}

// round 7
// speedup vs baseline: 7.4788x; 1.0592x over previous
#include <cuda_runtime.h>
#include <cuda_fp16.h>
#include <cstdint>

#define NE 8
#define NT 2048
#define ND 2048
#define NH 4096

// ---------------- scratch (static __device__, allocation-free) ----------------
__device__ __half g_x16[(long long)NE * NT * ND];
__device__ __half g_w1 [(long long)NE * ND * NH];
__device__ __half g_w3 [(long long)NE * ND * NH];
__device__ __half g_w2 [(long long)NE * NH * ND];
__device__ __half g_h16[(long long)NE * NT * NH];

// ---------------- PTX helpers (base-target sm_80+) ----------------
__device__ __forceinline__ void cp16s(uint32_t dst, const void* src) {
    asm volatile("cp.async.cg.shared.global [%0], [%1], 16;" :: "r"(dst), "l"(src));
}
__device__ __forceinline__ void ldsm4(uint32_t* r, uint32_t a) {
    asm volatile("ldmatrix.sync.aligned.m8n8.x4.shared.b16 {%0,%1,%2,%3}, [%4];"
                 : "=r"(r[0]), "=r"(r[1]), "=r"(r[2]), "=r"(r[3]) : "r"(a));
}
__device__ __forceinline__ void ldsm4t(uint32_t* r, uint32_t a) {
    asm volatile("ldmatrix.sync.aligned.m8n8.x4.trans.shared.b16 {%0,%1,%2,%3}, [%4];"
                 : "=r"(r[0]), "=r"(r[1]), "=r"(r[2]), "=r"(r[3]) : "r"(a));
}
__device__ __forceinline__ void mma16816(float* d, const uint32_t* a, const uint32_t* b) {
    asm volatile(
        "mma.sync.aligned.m16n8k16.row.col.f32.f16.f16.f32 "
        "{%0,%1,%2,%3}, {%4,%5,%6,%7}, {%8,%9}, {%0,%1,%2,%3};"
        : "+f"(d[0]), "+f"(d[1]), "+f"(d[2]), "+f"(d[3])
        : "r"(a[0]), "r"(a[1]), "r"(a[2]), "r"(a[3]), "r"(b[0]), "r"(b[1]));
}

// ---------------- conversion: fp32 -> fp16 (elementwise, 8/thread) ----------------
__global__ void conv_h16(const float4* __restrict__ in, __half2* __restrict__ o) {
    long long i = (long long)blockIdx.x * blockDim.x + threadIdx.x;
    float4 v0 = in[2 * i];
    float4 v1 = in[2 * i + 1];
    __half2 h[4];
    h[0] = __floats2half2_rn(v0.x, v0.y);
    h[1] = __floats2half2_rn(v0.z, v0.w);
    h[2] = __floats2half2_rn(v1.x, v1.y);
    h[3] = __floats2half2_rn(v1.z, v1.w);
    *(uint4*)(o + 4 * i) = *(uint4*)h;
}

// ---------------- GEMM13 (fused): h = silu(x@w1) * (x@w3) ----------------
// BM=128, BN=128, BK=64, 8 warps (2m x 4n), warp 64x32.
// SMEM: 4 slots x 48KB (A 16K | B1 16K | B3 16K), 3 in flight, 1 sync/chunk.
__global__ __launch_bounds__(256, 1)
void gemm13_fused(const __half* __restrict__ X, const __half* __restrict__ W1,
                  const __half* __restrict__ W3, __half* __restrict__ H)
{
    extern __shared__ __align__(128) char smem[];
    const uint32_t sbase = (uint32_t)__cvta_generic_to_shared(smem);
    const int tid = threadIdx.x;
    const int e  = blockIdx.z;
    const int n0 = blockIdx.x * 128;
    const int m0 = blockIdx.y * 128;

    const __half* pA  = X  + (long long)e * NT * ND + (long long)m0 * ND;
    const __half* pB1 = W1 + (long long)e * ND * NH + n0;
    const __half* pB3 = W3 + (long long)e * ND * NH + n0;

    const int warp = tid >> 5, lane = tid & 31;
    const int wm = (warp & 1) * 64;
    const int wn = (warp >> 1) * 32;

    float acc1[4][4][4], acc3[4][4][4];
    #pragma unroll
    for (int i = 0; i < 4; i++)
        #pragma unroll
        for (int j = 0; j < 4; j++)
            #pragma unroll
            for (int r = 0; r < 4; r++) { acc1[i][j][r] = 0.f; acc3[i][j][r] = 0.f; }

    auto load_stage = [&](int slot, int k0) {
        const uint32_t sb = sbase + slot * 49152;
        #pragma unroll
        for (int i = 0; i < 4; i++) {          // A: 128 rows x 8 chunks of 16B
            int id = tid + i * 256;
            int row = id >> 3, c = id & 7;
            cp16s(sb + row * 128 + ((c ^ (row & 7)) << 4),
                  pA + (long long)row * ND + k0 + c * 8);
        }
        #pragma unroll
        for (int i = 0; i < 4; i++) {          // B1/B3: 64 rows x 16 chunks
            int id = tid + i * 256;
            int row = id >> 4, c = id & 15;
            long long go = (long long)(k0 + row) * NH + c * 8;
            uint32_t so = sb + 16384 + row * 256 + ((c ^ (row & 7)) << 4);
            cp16s(so,         pB1 + go);
            cp16s(so + 16384, pB3 + go);
        }
        asm volatile("cp.async.commit_group;" ::: "memory");
    };

    load_stage(0, 0);
    load_stage(1, 64);
    load_stage(2, 128);

    const int NKC = ND / 64;
    for (int ch = 0; ch < NKC; ch++) {
        asm volatile("cp.async.wait_group 2;" ::: "memory");
        __syncthreads();
        // refill the slot consumed at iteration ch-1 (protected by the sync above)
        if (ch + 3 < NKC) load_stage((ch + 3) & 3, (ch + 3) * 64);
        else asm volatile("cp.async.commit_group;" ::: "memory");

        const uint32_t sb = sbase + (ch & 3) * 49152;
        #pragma unroll
        for (int ks = 0; ks < 4; ks++) {
            uint32_t av[4][4], b1[4][2], b3[4][2];
            #pragma unroll
            for (int mt = 0; mt < 4; mt++) {
                int row = wm + mt * 16 + (lane & 15);
                int cc  = ks * 2 + (lane >> 4);
                ldsm4(av[mt], sb + row * 128 + ((cc ^ (row & 7)) << 4));
            }
            #pragma unroll
            for (int np = 0; np < 2; np++) {   // x4.trans: two n8 tiles per load
                int kr = ks * 16 + (lane & 15);
                int nc = (wn >> 3) + np * 2 + (lane >> 4);
                uint32_t bd = sb + 16384 + kr * 256 + ((nc ^ (kr & 7)) << 4);
                uint32_t r[4];
                ldsm4t(r, bd);
                b1[np*2][0] = r[0]; b1[np*2][1] = r[1];
                b1[np*2+1][0] = r[2]; b1[np*2+1][1] = r[3];
                ldsm4t(r, bd + 16384);
                b3[np*2][0] = r[0]; b3[np*2][1] = r[1];
                b3[np*2+1][0] = r[2]; b3[np*2+1][1] = r[3];
            }
            #pragma unroll
            for (int mt = 0; mt < 4; mt++)
                #pragma unroll
                for (int nt = 0; nt < 4; nt++) {
                    mma16816(acc1[mt][nt], av[mt], b1[nt]);
                    mma16816(acc3[mt][nt], av[mt], b3[nt]);
                }
        }
    }

    // epilogue: h = silu(acc1) * acc3 -> fp16
    #pragma unroll
    for (int mt = 0; mt < 4; mt++)
        #pragma unroll
        for (int nt = 0; nt < 4; nt++) {
            const int row = m0 + wm + mt * 16 + (lane >> 2);
            const int col = n0 + wn + nt * 8 + (lane & 3) * 2;
            const long long i0 = ((long long)e * NT + row) * NH + col;
            const long long i1 = i0 + 8LL * NH;
            const float a0 = acc1[mt][nt][0], a1 = acc1[mt][nt][1];
            const float a2 = acc1[mt][nt][2], a3 = acc1[mt][nt][3];
            const float v0 = acc3[mt][nt][0] * a0 / (1.f + __expf(-a0));
            const float v1 = acc3[mt][nt][1] * a1 / (1.f + __expf(-a1));
            const float v2 = acc3[mt][nt][2] * a2 / (1.f + __expf(-a2));
            const float v3 = acc3[mt][nt][3] * a3 / (1.f + __expf(-a3));
            *(__half2*)&H[i0] = __floats2half2_rn(v0, v1);
            *(__half2*)&H[i1] = __floats2half2_rn(v2, v3);
        }
}

// ---------------- GEMM2: out = h @ w2 (fp32 out) ----------------
// BM=128, BN=128, BK=64; 3 slots x 32KB = 96KB -> 2 CTAs/SM.
__global__ __launch_bounds__(256, 2)
void gemm2_out(const __half* __restrict__ Hm, const __half* __restrict__ W2,
               float* __restrict__ Out)
{
    extern __shared__ __align__(128) char smem[];
    const uint32_t sbase = (uint32_t)__cvta_generic_to_shared(smem);
    const int tid = threadIdx.x;
    const int e  = blockIdx.z;
    const int n0 = blockIdx.x * 128;
    const int m0 = blockIdx.y * 128;

    const __half* pA = Hm + (long long)e * NT * NH + (long long)m0 * NH;
    const __half* pB = W2 + (long long)e * NH * ND + n0;

    const int warp = tid >> 5, lane = tid & 31;
    const int wm = (warp & 1) * 64;
    const int wn = (warp >> 1) * 32;

    float acc[4][4][4];
    #pragma unroll
    for (int i = 0; i < 4; i++)
        #pragma unroll
        for (int j = 0; j < 4; j++)
            #pragma unroll
            for (int r = 0; r < 4; r++) acc[i][j][r] = 0.f;

    auto load_stage = [&](int slot, int k0) {
        const uint32_t sb = sbase + slot * 32768;
        #pragma unroll
        for (int i = 0; i < 4; i++) {
            int id = tid + i * 256;
            int row = id >> 3, c = id & 7;
            cp16s(sb + row * 128 + ((c ^ (row & 7)) << 4),
                  pA + (long long)row * NH + k0 + c * 8);
        }
        #pragma unroll
        for (int i = 0; i < 4; i++) {
            int id = tid + i * 256;
            int row = id >> 4, c = id & 15;
            cp16s(sb + 16384 + row * 256 + ((c ^ (row & 7)) << 4),
                  pB + (long long)(k0 + row) * ND + c * 8);
        }
        asm volatile("cp.async.commit_group;" ::: "memory");
    };

    load_stage(0, 0);
    load_stage(1, 64);

    const int NKC = NH / 64;
    for (int ch = 0; ch < NKC; ch++) {
        asm volatile("cp.async.wait_group 1;" ::: "memory");
        __syncthreads();
        if (ch + 2 < NKC) load_stage((ch + 2) % 3, (ch + 2) * 64);
        else asm volatile("cp.async.commit_group;" ::: "memory");

        const uint32_t sb = sbase + (ch % 3) * 32768;
        #pragma unroll
        for (int ks = 0; ks < 4; ks++) {
            uint32_t av[4][4], bv[4][2];
            #pragma unroll
            for (int mt = 0; mt < 4; mt++) {
                int row = wm + mt * 16 + (lane & 15);
                int cc  = ks * 2 + (lane >> 4);
                ldsm4(av[mt], sb + row * 128 + ((cc ^ (row & 7)) << 4));
            }
            #pragma unroll
            for (int np = 0; np < 2; np++) {
                int kr = ks * 16 + (lane & 15);
                int nc = (wn >> 3) + np * 2 + (lane >> 4);
                uint32_t bd = sb + 16384 + kr * 256 + ((nc ^ (kr & 7)) << 4);
                uint32_t r[4];
                ldsm4t(r, bd);
                bv[np*2][0] = r[0]; bv[np*2][1] = r[1];
                bv[np*2+1][0] = r[2]; bv[np*2+1][1] = r[3];
            }
            #pragma unroll
            for (int mt = 0; mt < 4; mt++)
                #pragma unroll
                for (int nt = 0; nt < 4; nt++)
                    mma16816(acc[mt][nt], av[mt], bv[nt]);
        }
    }

    #pragma unroll
    for (int mt = 0; mt < 4; mt++)
        #pragma unroll
        for (int nt = 0; nt < 4; nt++) {
            const int row = m0 + wm + mt * 16 + (lane >> 2);
            const int col = n0 + wn + nt * 8 + (lane & 3) * 2;
            const long long i0 = ((long long)e * NT + row) * ND + col;
            const long long i1 = i0 + 8LL * ND;
            *(float2*)&Out[i0] = make_float2(acc[mt][nt][0], acc[mt][nt][1]);
            *(float2*)&Out[i1] = make_float2(acc[mt][nt][2], acc[mt][nt][3]);
        }
}

// ---------------- launch ----------------
// Inputs: x [E,T,D] fp32, w1 [E,D,H], w2 [E,H,D], w3 [E,D,H]. Output [E,T,D] fp32.
extern "C" void kernel_launch(void* const* d_in, const int* in_sizes, int n_in,
                              void* d_out, int out_size)
{
    const float* x  = (const float*)d_in[0];
    const float* w1 = (const float*)d_in[1];
    const float* w2 = (const float*)d_in[2];
    const float* w3 = (const float*)d_in[3];
    float* out = (float*)d_out;

    cudaFuncSetAttribute(gemm13_fused, cudaFuncAttributeMaxDynamicSharedMemorySize, 196608);
    cudaFuncSetAttribute(gemm2_out,    cudaFuncAttributeMaxDynamicSharedMemorySize, 98304);

    void *x16, *w1p, *w3p, *w2p, *h16;
    cudaGetSymbolAddress(&x16, g_x16);
    cudaGetSymbolAddress(&w1p, g_w1);
    cudaGetSymbolAddress(&w3p, g_w3);
    cudaGetSymbolAddress(&w2p, g_w2);
    cudaGetSymbolAddress(&h16, g_h16);

    const long long nx = (long long)NE * NT * ND;
    const long long nw = (long long)NE * ND * NH;
    conv_h16<<<(int)(nx / 8 / 256), 256>>>((const float4*)x,  (__half2*)x16);
    conv_h16<<<(int)(nw / 8 / 256), 256>>>((const float4*)w1, (__half2*)w1p);
    conv_h16<<<(int)(nw / 8 / 256), 256>>>((const float4*)w3, (__half2*)w3p);
    conv_h16<<<(int)(nw / 8 / 256), 256>>>((const float4*)w2, (__half2*)w2p);

    gemm13_fused<<<dim3(NH / 128, NT / 128, NE), 256, 196608>>>(
        (const __half*)x16, (const __half*)w1p, (const __half*)w3p, (__half*)h16);

    gemm2_out<<<dim3(ND / 128, NT / 128, NE), 256, 98304>>>(
        (const __half*)h16, (const __half*)w2p, out);
}

// round 8
// speedup vs baseline: 7.6469x; 1.0225x over previous
#include <cuda_runtime.h>
#include <cuda_fp16.h>
#include <cstdint>

#define NE 8
#define NT 2048
#define ND 2048
#define NH 4096

// ---------------- scratch (static __device__, allocation-free) ----------------
__device__ __half g_x16[(long long)NE * NT * ND];
__device__ __half g_w1 [(long long)NE * ND * NH];
__device__ __half g_w3 [(long long)NE * ND * NH];
__device__ __half g_w2 [(long long)NE * NH * ND];
__device__ __half g_h16[(long long)NE * NT * NH];

// ---------------- PTX helpers (base-target sm_80+) ----------------
__device__ __forceinline__ void cp16s(uint32_t dst, const void* src) {
    asm volatile("cp.async.cg.shared.global [%0], [%1], 16;" :: "r"(dst), "l"(src));
}
__device__ __forceinline__ void ldsm4(uint32_t* r, uint32_t a) {
    asm volatile("ldmatrix.sync.aligned.m8n8.x4.shared.b16 {%0,%1,%2,%3}, [%4];"
                 : "=r"(r[0]), "=r"(r[1]), "=r"(r[2]), "=r"(r[3]) : "r"(a));
}
__device__ __forceinline__ void ldsm4t(uint32_t* r, uint32_t a) {
    asm volatile("ldmatrix.sync.aligned.m8n8.x4.trans.shared.b16 {%0,%1,%2,%3}, [%4];"
                 : "=r"(r[0]), "=r"(r[1]), "=r"(r[2]), "=r"(r[3]) : "r"(a));
}
__device__ __forceinline__ void mma16816(float* d, const uint32_t* a, const uint32_t* b) {
    asm volatile(
        "mma.sync.aligned.m16n8k16.row.col.f32.f16.f16.f32 "
        "{%0,%1,%2,%3}, {%4,%5,%6,%7}, {%8,%9}, {%0,%1,%2,%3};"
        : "+f"(d[0]), "+f"(d[1]), "+f"(d[2]), "+f"(d[3])
        : "r"(a[0]), "r"(a[1]), "r"(a[2]), "r"(a[3]), "r"(b[0]), "r"(b[1]));
}

// ---------------- conversion: fp32 -> fp16 (elementwise, 8/thread) ----------------
__global__ void conv_h16(const float4* __restrict__ in, __half2* __restrict__ o) {
    long long i = (long long)blockIdx.x * blockDim.x + threadIdx.x;
    float4 v0 = in[2 * i];
    float4 v1 = in[2 * i + 1];
    __half2 h[4];
    h[0] = __floats2half2_rn(v0.x, v0.y);
    h[1] = __floats2half2_rn(v0.z, v0.w);
    h[2] = __floats2half2_rn(v1.x, v1.y);
    h[3] = __floats2half2_rn(v1.z, v1.w);
    *(uint4*)(o + 4 * i) = *(uint4*)h;
}

// ---------------- GEMM13 (fused): h = silu(x@w1) * (x@w3) ----------------
// BM=128, BN=128, BK=64; 512 threads = 16 warps (4m x 4n), warp tile 32x32.
// SMEM: 4 slots x 48KB (A 16K | B1 16K | B3 16K), 3 in flight, 1 sync/chunk.
__global__ __launch_bounds__(512, 1)
void gemm13_fused(const __half* __restrict__ X, const __half* __restrict__ W1,
                  const __half* __restrict__ W3, __half* __restrict__ H)
{
    extern __shared__ __align__(128) char smem[];
    const uint32_t sbase = (uint32_t)__cvta_generic_to_shared(smem);
    const int tid = threadIdx.x;
    const int e  = blockIdx.z;
    const int n0 = blockIdx.x * 128;
    const int m0 = blockIdx.y * 128;

    const __half* pA  = X  + (long long)e * NT * ND + (long long)m0 * ND;
    const __half* pB1 = W1 + (long long)e * ND * NH + n0;
    const __half* pB3 = W3 + (long long)e * ND * NH + n0;

    const int warp = tid >> 5, lane = tid & 31;
    const int wm = (warp & 3) * 32;      // 4 m-warps x 32 rows
    const int wn = (warp >> 2) * 32;     // 4 n-warps x 32 cols

    float acc1[2][4][4], acc3[2][4][4];
    #pragma unroll
    for (int i = 0; i < 2; i++)
        #pragma unroll
        for (int j = 0; j < 4; j++)
            #pragma unroll
            for (int r = 0; r < 4; r++) { acc1[i][j][r] = 0.f; acc3[i][j][r] = 0.f; }

    auto load_stage = [&](int slot, int k0) {
        const uint32_t sb = sbase + slot * 49152;
        #pragma unroll
        for (int i = 0; i < 2; i++) {          // A: 128 rows x 8 chunks of 16B
            int id = tid + i * 512;
            int row = id >> 3, c = id & 7;
            cp16s(sb + row * 128 + ((c ^ (row & 7)) << 4),
                  pA + (long long)row * ND + k0 + c * 8);
        }
        #pragma unroll
        for (int i = 0; i < 2; i++) {          // B1/B3: 64 rows x 16 chunks
            int id = tid + i * 512;
            int row = id >> 4, c = id & 15;
            long long go = (long long)(k0 + row) * NH + c * 8;
            uint32_t so = sb + 16384 + row * 256 + ((c ^ (row & 7)) << 4);
            cp16s(so,         pB1 + go);
            cp16s(so + 16384, pB3 + go);
        }
        asm volatile("cp.async.commit_group;" ::: "memory");
    };

    load_stage(0, 0);
    load_stage(1, 64);
    load_stage(2, 128);

    const int NKC = ND / 64;
    for (int ch = 0; ch < NKC; ch++) {
        asm volatile("cp.async.wait_group 2;" ::: "memory");
        __syncthreads();
        // refill the slot consumed at iteration ch-1 (protected by the sync above)
        if (ch + 3 < NKC) load_stage((ch + 3) & 3, (ch + 3) * 64);
        else asm volatile("cp.async.commit_group;" ::: "memory");

        const uint32_t sb = sbase + (ch & 3) * 49152;
        #pragma unroll
        for (int ks = 0; ks < 4; ks++) {
            uint32_t av[2][4], b1[4][2], b3[4][2];
            #pragma unroll
            for (int mt = 0; mt < 2; mt++) {
                int row = wm + mt * 16 + (lane & 15);
                int cc  = ks * 2 + (lane >> 4);
                ldsm4(av[mt], sb + row * 128 + ((cc ^ (row & 7)) << 4));
            }
            #pragma unroll
            for (int np = 0; np < 2; np++) {   // x4.trans: two n8 tiles per load
                int kr = ks * 16 + (lane & 15);
                int nc = (wn >> 3) + np * 2 + (lane >> 4);
                uint32_t bd = sb + 16384 + kr * 256 + ((nc ^ (kr & 7)) << 4);
                uint32_t r[4];
                ldsm4t(r, bd);
                b1[np*2][0] = r[0]; b1[np*2][1] = r[1];
                b1[np*2+1][0] = r[2]; b1[np*2+1][1] = r[3];
                ldsm4t(r, bd + 16384);
                b3[np*2][0] = r[0]; b3[np*2][1] = r[1];
                b3[np*2+1][0] = r[2]; b3[np*2+1][1] = r[3];
            }
            #pragma unroll
            for (int mt = 0; mt < 2; mt++)
                #pragma unroll
                for (int nt = 0; nt < 4; nt++) {
                    mma16816(acc1[mt][nt], av[mt], b1[nt]);
                    mma16816(acc3[mt][nt], av[mt], b3[nt]);
                }
        }
    }

    // epilogue: h = silu(acc1) * acc3 -> fp16
    #pragma unroll
    for (int mt = 0; mt < 2; mt++)
        #pragma unroll
        for (int nt = 0; nt < 4; nt++) {
            const int row = m0 + wm + mt * 16 + (lane >> 2);
            const int col = n0 + wn + nt * 8 + (lane & 3) * 2;
            const long long i0 = ((long long)e * NT + row) * NH + col;
            const long long i1 = i0 + 8LL * NH;
            const float a0 = acc1[mt][nt][0], a1 = acc1[mt][nt][1];
            const float a2 = acc1[mt][nt][2], a3 = acc1[mt][nt][3];
            const float v0 = acc3[mt][nt][0] * a0 / (1.f + __expf(-a0));
            const float v1 = acc3[mt][nt][1] * a1 / (1.f + __expf(-a1));
            const float v2 = acc3[mt][nt][2] * a2 / (1.f + __expf(-a2));
            const float v3 = acc3[mt][nt][3] * a3 / (1.f + __expf(-a3));
            *(__half2*)&H[i0] = __floats2half2_rn(v0, v1);
            *(__half2*)&H[i1] = __floats2half2_rn(v2, v3);
        }
}

// ---------------- GEMM2: out = h @ w2 (fp32 out) ----------------
// BM=128, BN=128, BK=64; 3 slots x 32KB = 96KB -> 2 CTAs/SM.
__global__ __launch_bounds__(256, 2)
void gemm2_out(const __half* __restrict__ Hm, const __half* __restrict__ W2,
               float* __restrict__ Out)
{
    extern __shared__ __align__(128) char smem[];
    const uint32_t sbase = (uint32_t)__cvta_generic_to_shared(smem);
    const int tid = threadIdx.x;
    const int e  = blockIdx.z;
    const int n0 = blockIdx.x * 128;
    const int m0 = blockIdx.y * 128;

    const __half* pA = Hm + (long long)e * NT * NH + (long long)m0 * NH;
    const __half* pB = W2 + (long long)e * NH * ND + n0;

    const int warp = tid >> 5, lane = tid & 31;
    const int wm = (warp & 1) * 64;
    const int wn = (warp >> 1) * 32;

    float acc[4][4][4];
    #pragma unroll
    for (int i = 0; i < 4; i++)
        #pragma unroll
        for (int j = 0; j < 4; j++)
            #pragma unroll
            for (int r = 0; r < 4; r++) acc[i][j][r] = 0.f;

    auto load_stage = [&](int slot, int k0) {
        const uint32_t sb = sbase + slot * 32768;
        #pragma unroll
        for (int i = 0; i < 4; i++) {
            int id = tid + i * 256;
            int row = id >> 3, c = id & 7;
            cp16s(sb + row * 128 + ((c ^ (row & 7)) << 4),
                  pA + (long long)row * NH + k0 + c * 8);
        }
        #pragma unroll
        for (int i = 0; i < 4; i++) {
            int id = tid + i * 256;
            int row = id >> 4, c = id & 15;
            cp16s(sb + 16384 + row * 256 + ((c ^ (row & 7)) << 4),
                  pB + (long long)(k0 + row) * ND + c * 8);
        }
        asm volatile("cp.async.commit_group;" ::: "memory");
    };

    load_stage(0, 0);
    load_stage(1, 64);

    const int NKC = NH / 64;
    for (int ch = 0; ch < NKC; ch++) {
        asm volatile("cp.async.wait_group 1;" ::: "memory");
        __syncthreads();
        if (ch + 2 < NKC) load_stage((ch + 2) % 3, (ch + 2) * 64);
        else asm volatile("cp.async.commit_group;" ::: "memory");

        const uint32_t sb = sbase + (ch % 3) * 32768;
        #pragma unroll
        for (int ks = 0; ks < 4; ks++) {
            uint32_t av[4][4], bv[4][2];
            #pragma unroll
            for (int mt = 0; mt < 4; mt++) {
                int row = wm + mt * 16 + (lane & 15);
                int cc  = ks * 2 + (lane >> 4);
                ldsm4(av[mt], sb + row * 128 + ((cc ^ (row & 7)) << 4));
            }
            #pragma unroll
            for (int np = 0; np < 2; np++) {
                int kr = ks * 16 + (lane & 15);
                int nc = (wn >> 3) + np * 2 + (lane >> 4);
                uint32_t bd = sb + 16384 + kr * 256 + ((nc ^ (kr & 7)) << 4);
                uint32_t r[4];
                ldsm4t(r, bd);
                bv[np*2][0] = r[0]; bv[np*2][1] = r[1];
                bv[np*2+1][0] = r[2]; bv[np*2+1][1] = r[3];
            }
            #pragma unroll
            for (int mt = 0; mt < 4; mt++)
                #pragma unroll
                for (int nt = 0; nt < 4; nt++)
                    mma16816(acc[mt][nt], av[mt], bv[nt]);
        }
    }

    #pragma unroll
    for (int mt = 0; mt < 4; mt++)
        #pragma unroll
        for (int nt = 0; nt < 4; nt++) {
            const int row = m0 + wm + mt * 16 + (lane >> 2);
            const int col = n0 + wn + nt * 8 + (lane & 3) * 2;
            const long long i0 = ((long long)e * NT + row) * ND + col;
            const long long i1 = i0 + 8LL * ND;
            *(float2*)&Out[i0] = make_float2(acc[mt][nt][0], acc[mt][nt][1]);
            *(float2*)&Out[i1] = make_float2(acc[mt][nt][2], acc[mt][nt][3]);
        }
}

// ---------------- launch ----------------
// Inputs: x [E,T,D] fp32, w1 [E,D,H], w2 [E,H,D], w3 [E,D,H]. Output [E,T,D] fp32.
extern "C" void kernel_launch(void* const* d_in, const int* in_sizes, int n_in,
                              void* d_out, int out_size)
{
    const float* x  = (const float*)d_in[0];
    const float* w1 = (const float*)d_in[1];
    const float* w2 = (const float*)d_in[2];
    const float* w3 = (const float*)d_in[3];
    float* out = (float*)d_out;

    cudaFuncSetAttribute(gemm13_fused, cudaFuncAttributeMaxDynamicSharedMemorySize, 196608);
    cudaFuncSetAttribute(gemm2_out,    cudaFuncAttributeMaxDynamicSharedMemorySize, 98304);

    void *x16, *w1p, *w3p, *w2p, *h16;
    cudaGetSymbolAddress(&x16, g_x16);
    cudaGetSymbolAddress(&w1p, g_w1);
    cudaGetSymbolAddress(&w3p, g_w3);
    cudaGetSymbolAddress(&w2p, g_w2);
    cudaGetSymbolAddress(&h16, g_h16);

    const long long nx = (long long)NE * NT * ND;
    const long long nw = (long long)NE * ND * NH;
    conv_h16<<<(int)(nx / 8 / 256), 256>>>((const float4*)x,  (__half2*)x16);
    conv_h16<<<(int)(nw / 8 / 256), 256>>>((const float4*)w1, (__half2*)w1p);
    conv_h16<<<(int)(nw / 8 / 256), 256>>>((const float4*)w3, (__half2*)w3p);
    conv_h16<<<(int)(nw / 8 / 256), 256>>>((const float4*)w2, (__half2*)w2p);

    gemm13_fused<<<dim3(NH / 128, NT / 128, NE), 512, 196608>>>(
        (const __half*)x16, (const __half*)w1p, (const __half*)w3p, (__half*)h16);

    gemm2_out<<<dim3(ND / 128, NT / 128, NE), 256, 98304>>>(
        (const __half*)h16, (const __half*)w2p, out);
}

// round 9
// speedup vs baseline: 8.1627x; 1.0675x over previous
#include <cuda_runtime.h>
#include <cuda_fp16.h>
#include <cstdint>

#define NE 8
#define NT 2048
#define ND 2048
#define NH 4096

// ---------------- scratch (static __device__, allocation-free) ----------------
__device__ __half g_x16[(long long)NE * NT * ND];
__device__ __half g_w1 [(long long)NE * ND * NH];
__device__ __half g_w3 [(long long)NE * ND * NH];
__device__ __half g_w2 [(long long)NE * NH * ND];
__device__ __half g_h16[(long long)NE * NT * NH];

// ---------------- PTX helpers (base-target sm_80+) ----------------
__device__ __forceinline__ void cp16s(uint32_t dst, const void* src) {
    asm volatile("cp.async.cg.shared.global [%0], [%1], 16;" :: "r"(dst), "l"(src));
}
__device__ __forceinline__ void ldsm4(uint32_t* r, uint32_t a) {
    asm volatile("ldmatrix.sync.aligned.m8n8.x4.shared.b16 {%0,%1,%2,%3}, [%4];"
                 : "=r"(r[0]), "=r"(r[1]), "=r"(r[2]), "=r"(r[3]) : "r"(a));
}
__device__ __forceinline__ void ldsm4t(uint32_t* r, uint32_t a) {
    asm volatile("ldmatrix.sync.aligned.m8n8.x4.trans.shared.b16 {%0,%1,%2,%3}, [%4];"
                 : "=r"(r[0]), "=r"(r[1]), "=r"(r[2]), "=r"(r[3]) : "r"(a));
}
__device__ __forceinline__ void mma16816(float* d, const uint32_t* a, const uint32_t* b) {
    asm volatile(
        "mma.sync.aligned.m16n8k16.row.col.f32.f16.f16.f32 "
        "{%0,%1,%2,%3}, {%4,%5,%6,%7}, {%8,%9}, {%0,%1,%2,%3};"
        : "+f"(d[0]), "+f"(d[1]), "+f"(d[2]), "+f"(d[3])
        : "r"(a[0]), "r"(a[1]), "r"(a[2]), "r"(a[3]), "r"(b[0]), "r"(b[1]));
}

// ---------------- conversion: fp32 -> fp16 (elementwise, 8/thread) ----------------
__global__ void conv_h16(const float4* __restrict__ in, __half2* __restrict__ o) {
    long long i = (long long)blockIdx.x * blockDim.x + threadIdx.x;
    float4 v0 = in[2 * i];
    float4 v1 = in[2 * i + 1];
    __half2 h[4];
    h[0] = __floats2half2_rn(v0.x, v0.y);
    h[1] = __floats2half2_rn(v0.z, v0.w);
    h[2] = __floats2half2_rn(v1.x, v1.y);
    h[3] = __floats2half2_rn(v1.z, v1.w);
    *(uint4*)(o + 4 * i) = *(uint4*)h;
}

// ---------------- GEMM13 (fused): h = silu(x@w1) * (x@w3) ----------------
// BM=128, BN=64, BK=64; 256 threads = 8 warps (2m x 4n), warp tile 64x16.
// SMEM: 3 slots x 32KB (A 16K | B1 8K | B3 8K) -> 2 CTAs/SM. Grid 8192 CTAs.
__global__ __launch_bounds__(256, 2)
void gemm13_fused(const __half* __restrict__ X, const __half* __restrict__ W1,
                  const __half* __restrict__ W3, __half* __restrict__ H)
{
    extern __shared__ __align__(128) char smem[];
    const uint32_t sbase = (uint32_t)__cvta_generic_to_shared(smem);
    const int tid = threadIdx.x;
    const int e  = blockIdx.z;
    const int n0 = blockIdx.x * 64;
    const int m0 = blockIdx.y * 128;

    const __half* pA  = X  + (long long)e * NT * ND + (long long)m0 * ND;
    const __half* pB1 = W1 + (long long)e * ND * NH + n0;
    const __half* pB3 = W3 + (long long)e * ND * NH + n0;

    const int warp = tid >> 5, lane = tid & 31;
    const int wm = (warp & 1) * 64;      // 2 m-warps x 64 rows
    const int wn = (warp >> 1) * 16;     // 4 n-warps x 16 cols

    float acc1[4][2][4], acc3[4][2][4];
    #pragma unroll
    for (int i = 0; i < 4; i++)
        #pragma unroll
        for (int j = 0; j < 2; j++)
            #pragma unroll
            for (int r = 0; r < 4; r++) { acc1[i][j][r] = 0.f; acc3[i][j][r] = 0.f; }

    auto load_stage = [&](int slot, int k0) {
        const uint32_t sb = sbase + slot * 32768;
        #pragma unroll
        for (int i = 0; i < 4; i++) {          // A: 128 rows x 8 chunks of 16B
            int id = tid + i * 256;
            int row = id >> 3, c = id & 7;
            cp16s(sb + row * 128 + ((c ^ (row & 7)) << 4),
                  pA + (long long)row * ND + k0 + c * 8);
        }
        #pragma unroll
        for (int i = 0; i < 2; i++) {          // B1/B3: 64 rows x 8 chunks (128B rows)
            int id = tid + i * 256;
            int row = id >> 3, c = id & 7;
            long long go = (long long)(k0 + row) * NH + c * 8;
            uint32_t so = sb + 16384 + row * 128 + ((c ^ (row & 7)) << 4);
            cp16s(so,        pB1 + go);
            cp16s(so + 8192, pB3 + go);
        }
        asm volatile("cp.async.commit_group;" ::: "memory");
    };

    load_stage(0, 0);
    load_stage(1, 64);

    const int NKC = ND / 64;
    for (int ch = 0; ch < NKC; ch++) {
        asm volatile("cp.async.wait_group 1;" ::: "memory");
        __syncthreads();
        if (ch + 2 < NKC) load_stage((ch + 2) % 3, (ch + 2) * 64);
        else asm volatile("cp.async.commit_group;" ::: "memory");

        const uint32_t sb = sbase + (ch % 3) * 32768;
        #pragma unroll
        for (int ks = 0; ks < 4; ks++) {
            uint32_t av[4][4], b1[2][2], b3[2][2];
            #pragma unroll
            for (int mt = 0; mt < 4; mt++) {
                int row = wm + mt * 16 + (lane & 15);
                int cc  = ks * 2 + (lane >> 4);
                ldsm4(av[mt], sb + row * 128 + ((cc ^ (row & 7)) << 4));
            }
            {   // one x4.trans per matrix covers both n8 tiles of this warp
                int kr = ks * 16 + (lane & 15);
                int nc = (wn >> 3) + (lane >> 4);
                uint32_t bd = sb + 16384 + kr * 128 + ((nc ^ (kr & 7)) << 4);
                uint32_t r[4];
                ldsm4t(r, bd);
                b1[0][0] = r[0]; b1[0][1] = r[1];
                b1[1][0] = r[2]; b1[1][1] = r[3];
                ldsm4t(r, bd + 8192);
                b3[0][0] = r[0]; b3[0][1] = r[1];
                b3[1][0] = r[2]; b3[1][1] = r[3];
            }
            #pragma unroll
            for (int mt = 0; mt < 4; mt++)
                #pragma unroll
                for (int nt = 0; nt < 2; nt++) {
                    mma16816(acc1[mt][nt], av[mt], b1[nt]);
                    mma16816(acc3[mt][nt], av[mt], b3[nt]);
                }
        }
    }

    // epilogue: h = silu(acc1) * acc3 -> fp16
    #pragma unroll
    for (int mt = 0; mt < 4; mt++)
        #pragma unroll
        for (int nt = 0; nt < 2; nt++) {
            const int row = m0 + wm + mt * 16 + (lane >> 2);
            const int col = n0 + wn + nt * 8 + (lane & 3) * 2;
            const long long i0 = ((long long)e * NT + row) * NH + col;
            const long long i1 = i0 + 8LL * NH;
            const float a0 = acc1[mt][nt][0], a1 = acc1[mt][nt][1];
            const float a2 = acc1[mt][nt][2], a3 = acc1[mt][nt][3];
            const float v0 = acc3[mt][nt][0] * a0 / (1.f + __expf(-a0));
            const float v1 = acc3[mt][nt][1] * a1 / (1.f + __expf(-a1));
            const float v2 = acc3[mt][nt][2] * a2 / (1.f + __expf(-a2));
            const float v3 = acc3[mt][nt][3] * a3 / (1.f + __expf(-a3));
            *(__half2*)&H[i0] = __floats2half2_rn(v0, v1);
            *(__half2*)&H[i1] = __floats2half2_rn(v2, v3);
        }
}

// ---------------- GEMM2: out = h @ w2 (fp32 out) ----------------
// BM=128, BN=128, BK=64; 3 slots x 32KB = 96KB -> 2 CTAs/SM.
__global__ __launch_bounds__(256, 2)
void gemm2_out(const __half* __restrict__ Hm, const __half* __restrict__ W2,
               float* __restrict__ Out)
{
    extern __shared__ __align__(128) char smem[];
    const uint32_t sbase = (uint32_t)__cvta_generic_to_shared(smem);
    const int tid = threadIdx.x;
    const int e  = blockIdx.z;
    const int n0 = blockIdx.x * 128;
    const int m0 = blockIdx.y * 128;

    const __half* pA = Hm + (long long)e * NT * NH + (long long)m0 * NH;
    const __half* pB = W2 + (long long)e * NH * ND + n0;

    const int warp = tid >> 5, lane = tid & 31;
    const int wm = (warp & 1) * 64;
    const int wn = (warp >> 1) * 32;

    float acc[4][4][4];
    #pragma unroll
    for (int i = 0; i < 4; i++)
        #pragma unroll
        for (int j = 0; j < 4; j++)
            #pragma unroll
            for (int r = 0; r < 4; r++) acc[i][j][r] = 0.f;

    auto load_stage = [&](int slot, int k0) {
        const uint32_t sb = sbase + slot * 32768;
        #pragma unroll
        for (int i = 0; i < 4; i++) {
            int id = tid + i * 256;
            int row = id >> 3, c = id & 7;
            cp16s(sb + row * 128 + ((c ^ (row & 7)) << 4),
                  pA + (long long)row * NH + k0 + c * 8);
        }
        #pragma unroll
        for (int i = 0; i < 4; i++) {
            int id = tid + i * 256;
            int row = id >> 4, c = id & 15;
            cp16s(sb + 16384 + row * 256 + ((c ^ (row & 7)) << 4),
                  pB + (long long)(k0 + row) * ND + c * 8);
        }
        asm volatile("cp.async.commit_group;" ::: "memory");
    };

    load_stage(0, 0);
    load_stage(1, 64);

    const int NKC = NH / 64;
    for (int ch = 0; ch < NKC; ch++) {
        asm volatile("cp.async.wait_group 1;" ::: "memory");
        __syncthreads();
        if (ch + 2 < NKC) load_stage((ch + 2) % 3, (ch + 2) * 64);
        else asm volatile("cp.async.commit_group;" ::: "memory");

        const uint32_t sb = sbase + (ch % 3) * 32768;
        #pragma unroll
        for (int ks = 0; ks < 4; ks++) {
            uint32_t av[4][4], bv[4][2];
            #pragma unroll
            for (int mt = 0; mt < 4; mt++) {
                int row = wm + mt * 16 + (lane & 15);
                int cc  = ks * 2 + (lane >> 4);
                ldsm4(av[mt], sb + row * 128 + ((cc ^ (row & 7)) << 4));
            }
            #pragma unroll
            for (int np = 0; np < 2; np++) {
                int kr = ks * 16 + (lane & 15);
                int nc = (wn >> 3) + np * 2 + (lane >> 4);
                uint32_t bd = sb + 16384 + kr * 256 + ((nc ^ (kr & 7)) << 4);
                uint32_t r[4];
                ldsm4t(r, bd);
                bv[np*2][0] = r[0]; bv[np*2][1] = r[1];
                bv[np*2+1][0] = r[2]; bv[np*2+1][1] = r[3];
            }
            #pragma unroll
            for (int mt = 0; mt < 4; mt++)
                #pragma unroll
                for (int nt = 0; nt < 4; nt++)
                    mma16816(acc[mt][nt], av[mt], bv[nt]);
        }
    }

    #pragma unroll
    for (int mt = 0; mt < 4; mt++)
        #pragma unroll
        for (int nt = 0; nt < 4; nt++) {
            const int row = m0 + wm + mt * 16 + (lane >> 2);
            const int col = n0 + wn + nt * 8 + (lane & 3) * 2;
            const long long i0 = ((long long)e * NT + row) * ND + col;
            const long long i1 = i0 + 8LL * ND;
            *(float2*)&Out[i0] = make_float2(acc[mt][nt][0], acc[mt][nt][1]);
            *(float2*)&Out[i1] = make_float2(acc[mt][nt][2], acc[mt][nt][3]);
        }
}

// ---------------- launch ----------------
// Inputs: x [E,T,D] fp32, w1 [E,D,H], w2 [E,H,D], w3 [E,D,H]. Output [E,T,D] fp32.
extern "C" void kernel_launch(void* const* d_in, const int* in_sizes, int n_in,
                              void* d_out, int out_size)
{
    const float* x  = (const float*)d_in[0];
    const float* w1 = (const float*)d_in[1];
    const float* w2 = (const float*)d_in[2];
    const float* w3 = (const float*)d_in[3];
    float* out = (float*)d_out;

    cudaFuncSetAttribute(gemm13_fused, cudaFuncAttributeMaxDynamicSharedMemorySize, 98304);
    cudaFuncSetAttribute(gemm2_out,    cudaFuncAttributeMaxDynamicSharedMemorySize, 98304);

    void *x16, *w1p, *w3p, *w2p, *h16;
    cudaGetSymbolAddress(&x16, g_x16);
    cudaGetSymbolAddress(&w1p, g_w1);
    cudaGetSymbolAddress(&w3p, g_w3);
    cudaGetSymbolAddress(&w2p, g_w2);
    cudaGetSymbolAddress(&h16, g_h16);

    const long long nx = (long long)NE * NT * ND;
    const long long nw = (long long)NE * ND * NH;
    conv_h16<<<(int)(nx / 8 / 256), 256>>>((const float4*)x,  (__half2*)x16);
    conv_h16<<<(int)(nw / 8 / 256), 256>>>((const float4*)w1, (__half2*)w1p);
    conv_h16<<<(int)(nw / 8 / 256), 256>>>((const float4*)w3, (__half2*)w3p);
    conv_h16<<<(int)(nw / 8 / 256), 256>>>((const float4*)w2, (__half2*)w2p);

    gemm13_fused<<<dim3(NH / 64, NT / 128, NE), 256, 98304>>>(
        (const __half*)x16, (const __half*)w1p, (const __half*)w3p, (__half*)h16);

    gemm2_out<<<dim3(ND / 128, NT / 128, NE), 256, 98304>>>(
        (const __half*)h16, (const __half*)w2p, out);
}

// round 10
// speedup vs baseline: 8.2381x; 1.0092x over previous
#include <cuda_runtime.h>
#include <cuda_fp16.h>
#include <cstdint>

#define NE 8
#define NT 2048
#define ND 2048
#define NH 4096

// ---------------- scratch (static __device__, allocation-free) ----------------
__device__ __half g_x16[(long long)NE * NT * ND];
__device__ __half g_w1 [(long long)NE * ND * NH];
__device__ __half g_w3 [(long long)NE * ND * NH];
__device__ __half g_w2 [(long long)NE * NH * ND];
__device__ __half g_h16[(long long)NE * NT * NH];

// ---------------- PTX helpers (base-target sm_80+) ----------------
__device__ __forceinline__ void cp16s(uint32_t dst, const void* src) {
    asm volatile("cp.async.cg.shared.global [%0], [%1], 16;" :: "r"(dst), "l"(src));
}
__device__ __forceinline__ void ldsm4(uint32_t* r, uint32_t a) {
    asm volatile("ldmatrix.sync.aligned.m8n8.x4.shared.b16 {%0,%1,%2,%3}, [%4];"
                 : "=r"(r[0]), "=r"(r[1]), "=r"(r[2]), "=r"(r[3]) : "r"(a));
}
__device__ __forceinline__ void ldsm4t(uint32_t* r, uint32_t a) {
    asm volatile("ldmatrix.sync.aligned.m8n8.x4.trans.shared.b16 {%0,%1,%2,%3}, [%4];"
                 : "=r"(r[0]), "=r"(r[1]), "=r"(r[2]), "=r"(r[3]) : "r"(a));
}
__device__ __forceinline__ void mma16816(float* d, const uint32_t* a, const uint32_t* b) {
    asm volatile(
        "mma.sync.aligned.m16n8k16.row.col.f32.f16.f16.f32 "
        "{%0,%1,%2,%3}, {%4,%5,%6,%7}, {%8,%9}, {%0,%1,%2,%3};"
        : "+f"(d[0]), "+f"(d[1]), "+f"(d[2]), "+f"(d[3])
        : "r"(a[0]), "r"(a[1]), "r"(a[2]), "r"(a[3]), "r"(b[0]), "r"(b[1]));
}

// 8-element fp32 -> fp16 convert unit
__device__ __forceinline__ void conv8(const float4* __restrict__ src,
                                      __half2* __restrict__ dst, long long u) {
    float4 v0 = src[2 * u];
    float4 v1 = src[2 * u + 1];
    __half2 h[4];
    h[0] = __floats2half2_rn(v0.x, v0.y);
    h[1] = __floats2half2_rn(v0.z, v0.w);
    h[2] = __floats2half2_rn(v1.x, v1.y);
    h[3] = __floats2half2_rn(v1.z, v1.w);
    *(uint4*)(dst + 4 * u) = *(uint4*)h;
}

// ---------------- merged conversion: x, w1, w3 in one launch ----------------
// Unit = 8 elements. x: 4194304 units, w1: 8388608, w3: 8388608 -> 20971520 units.
__global__ void conv3_kernel(const float4* __restrict__ X, const float4* __restrict__ W1,
                             const float4* __restrict__ W3) {
    const long long UX = (long long)NE * NT * ND / 8;
    const long long UW = (long long)NE * ND * NH / 8;
    long long u = (long long)blockIdx.x * blockDim.x + threadIdx.x;
    if (u < UX)            conv8(X,  (__half2*)g_x16, u);
    else if (u < UX + UW)  conv8(W1, (__half2*)g_w1,  u - UX);
    else                   conv8(W3, (__half2*)g_w3,  u - UX - UW);
}

// ---------------- GEMM13 (fused): h = silu(x@w1) * (x@w3)  [+ piggybacked w2 conv] ----------------
// BM=128, BN=64, BK=64; 256 threads = 8 warps (2m x 4n), warp tile 64x16.
// SMEM: 3 slots x 32KB (A 16K | B1 8K | B3 8K) -> 2 CTAs/SM.
// blockIdx.z == NE plane: 1024 CTAs convert w2 fp32->fp16 (gemm2 consumes it next launch).
__global__ __launch_bounds__(256, 2)
void gemm13_fused(const __half* __restrict__ X, const __half* __restrict__ W1,
                  const __half* __restrict__ W3, __half* __restrict__ H,
                  const float4* __restrict__ W2f)
{
    if (blockIdx.z == NE) {
        // w2 conversion plane: 1024 CTAs x 256 threads, grid-stride over 8.39M units
        const long long UW = (long long)NE * NH * ND / 8;
        const long long stride = (long long)gridDim.x * gridDim.y * blockDim.x;
        long long id = ((long long)blockIdx.y * gridDim.x + blockIdx.x) * blockDim.x
                       + threadIdx.x;
        for (long long u = id; u < UW; u += stride)
            conv8(W2f, (__half2*)g_w2, u);
        return;
    }

    extern __shared__ __align__(128) char smem[];
    const uint32_t sbase = (uint32_t)__cvta_generic_to_shared(smem);
    const int tid = threadIdx.x;
    const int e  = blockIdx.z;
    const int n0 = blockIdx.x * 64;
    const int m0 = blockIdx.y * 128;

    const __half* pA  = X  + (long long)e * NT * ND + (long long)m0 * ND;
    const __half* pB1 = W1 + (long long)e * ND * NH + n0;
    const __half* pB3 = W3 + (long long)e * ND * NH + n0;

    const int warp = tid >> 5, lane = tid & 31;
    const int wm = (warp & 1) * 64;      // 2 m-warps x 64 rows
    const int wn = (warp >> 1) * 16;     // 4 n-warps x 16 cols

    float acc1[4][2][4], acc3[4][2][4];
    #pragma unroll
    for (int i = 0; i < 4; i++)
        #pragma unroll
        for (int j = 0; j < 2; j++)
            #pragma unroll
            for (int r = 0; r < 4; r++) { acc1[i][j][r] = 0.f; acc3[i][j][r] = 0.f; }

    auto load_stage = [&](int slot, int k0) {
        const uint32_t sb = sbase + slot * 32768;
        #pragma unroll
        for (int i = 0; i < 4; i++) {          // A: 128 rows x 8 chunks of 16B
            int id = tid + i * 256;
            int row = id >> 3, c = id & 7;
            cp16s(sb + row * 128 + ((c ^ (row & 7)) << 4),
                  pA + (long long)row * ND + k0 + c * 8);
        }
        #pragma unroll
        for (int i = 0; i < 2; i++) {          // B1/B3: 64 rows x 8 chunks (128B rows)
            int id = tid + i * 256;
            int row = id >> 3, c = id & 7;
            long long go = (long long)(k0 + row) * NH + c * 8;
            uint32_t so = sb + 16384 + row * 128 + ((c ^ (row & 7)) << 4);
            cp16s(so,        pB1 + go);
            cp16s(so + 8192, pB3 + go);
        }
        asm volatile("cp.async.commit_group;" ::: "memory");
    };

    load_stage(0, 0);
    load_stage(1, 64);

    const int NKC = ND / 64;
    for (int ch = 0; ch < NKC; ch++) {
        asm volatile("cp.async.wait_group 1;" ::: "memory");
        __syncthreads();
        if (ch + 2 < NKC) load_stage((ch + 2) % 3, (ch + 2) * 64);
        else asm volatile("cp.async.commit_group;" ::: "memory");

        const uint32_t sb = sbase + (ch % 3) * 32768;
        #pragma unroll
        for (int ks = 0; ks < 4; ks++) {
            uint32_t av[4][4], b1[2][2], b3[2][2];
            #pragma unroll
            for (int mt = 0; mt < 4; mt++) {
                int row = wm + mt * 16 + (lane & 15);
                int cc  = ks * 2 + (lane >> 4);
                ldsm4(av[mt], sb + row * 128 + ((cc ^ (row & 7)) << 4));
            }
            {   // one x4.trans per matrix covers both n8 tiles of this warp
                int kr = ks * 16 + (lane & 15);
                int nc = (wn >> 3) + (lane >> 4);
                uint32_t bd = sb + 16384 + kr * 128 + ((nc ^ (kr & 7)) << 4);
                uint32_t r[4];
                ldsm4t(r, bd);
                b1[0][0] = r[0]; b1[0][1] = r[1];
                b1[1][0] = r[2]; b1[1][1] = r[3];
                ldsm4t(r, bd + 8192);
                b3[0][0] = r[0]; b3[0][1] = r[1];
                b3[1][0] = r[2]; b3[1][1] = r[3];
            }
            #pragma unroll
            for (int mt = 0; mt < 4; mt++)
                #pragma unroll
                for (int nt = 0; nt < 2; nt++) {
                    mma16816(acc1[mt][nt], av[mt], b1[nt]);
                    mma16816(acc3[mt][nt], av[mt], b3[nt]);
                }
        }
    }

    // epilogue: h = silu(acc1) * acc3 -> fp16
    #pragma unroll
    for (int mt = 0; mt < 4; mt++)
        #pragma unroll
        for (int nt = 0; nt < 2; nt++) {
            const int row = m0 + wm + mt * 16 + (lane >> 2);
            const int col = n0 + wn + nt * 8 + (lane & 3) * 2;
            const long long i0 = ((long long)e * NT + row) * NH + col;
            const long long i1 = i0 + 8LL * NH;
            const float a0 = acc1[mt][nt][0], a1 = acc1[mt][nt][1];
            const float a2 = acc1[mt][nt][2], a3 = acc1[mt][nt][3];
            const float v0 = acc3[mt][nt][0] * a0 / (1.f + __expf(-a0));
            const float v1 = acc3[mt][nt][1] * a1 / (1.f + __expf(-a1));
            const float v2 = acc3[mt][nt][2] * a2 / (1.f + __expf(-a2));
            const float v3 = acc3[mt][nt][3] * a3 / (1.f + __expf(-a3));
            *(__half2*)&H[i0] = __floats2half2_rn(v0, v1);
            *(__half2*)&H[i1] = __floats2half2_rn(v2, v3);
        }
}

// ---------------- GEMM2: out = h @ w2 (fp32 out) ----------------
// BM=128, BN=128, BK=64; 3 slots x 32KB = 96KB -> 2 CTAs/SM.
__global__ __launch_bounds__(256, 2)
void gemm2_out(const __half* __restrict__ Hm, const __half* __restrict__ W2,
               float* __restrict__ Out)
{
    extern __shared__ __align__(128) char smem[];
    const uint32_t sbase = (uint32_t)__cvta_generic_to_shared(smem);
    const int tid = threadIdx.x;
    const int e  = blockIdx.z;
    const int n0 = blockIdx.x * 128;
    const int m0 = blockIdx.y * 128;

    const __half* pA = Hm + (long long)e * NT * NH + (long long)m0 * NH;
    const __half* pB = W2 + (long long)e * NH * ND + n0;

    const int warp = tid >> 5, lane = tid & 31;
    const int wm = (warp & 1) * 64;
    const int wn = (warp >> 1) * 32;

    float acc[4][4][4];
    #pragma unroll
    for (int i = 0; i < 4; i++)
        #pragma unroll
        for (int j = 0; j < 4; j++)
            #pragma unroll
            for (int r = 0; r < 4; r++) acc[i][j][r] = 0.f;

    auto load_stage = [&](int slot, int k0) {
        const uint32_t sb = sbase + slot * 32768;
        #pragma unroll
        for (int i = 0; i < 4; i++) {
            int id = tid + i * 256;
            int row = id >> 3, c = id & 7;
            cp16s(sb + row * 128 + ((c ^ (row & 7)) << 4),
                  pA + (long long)row * NH + k0 + c * 8);
        }
        #pragma unroll
        for (int i = 0; i < 4; i++) {
            int id = tid + i * 256;
            int row = id >> 4, c = id & 15;
            cp16s(sb + 16384 + row * 256 + ((c ^ (row & 7)) << 4),
                  pB + (long long)(k0 + row) * ND + c * 8);
        }
        asm volatile("cp.async.commit_group;" ::: "memory");
    };

    load_stage(0, 0);
    load_stage(1, 64);

    const int NKC = NH / 64;
    for (int ch = 0; ch < NKC; ch++) {
        asm volatile("cp.async.wait_group 1;" ::: "memory");
        __syncthreads();
        if (ch + 2 < NKC) load_stage((ch + 2) % 3, (ch + 2) * 64);
        else asm volatile("cp.async.commit_group;" ::: "memory");

        const uint32_t sb = sbase + (ch % 3) * 32768;
        #pragma unroll
        for (int ks = 0; ks < 4; ks++) {
            uint32_t av[4][4], bv[4][2];
            #pragma unroll
            for (int mt = 0; mt < 4; mt++) {
                int row = wm + mt * 16 + (lane & 15);
                int cc  = ks * 2 + (lane >> 4);
                ldsm4(av[mt], sb + row * 128 + ((cc ^ (row & 7)) << 4));
            }
            #pragma unroll
            for (int np = 0; np < 2; np++) {
                int kr = ks * 16 + (lane & 15);
                int nc = (wn >> 3) + np * 2 + (lane >> 4);
                uint32_t bd = sb + 16384 + kr * 256 + ((nc ^ (kr & 7)) << 4);
                uint32_t r[4];
                ldsm4t(r, bd);
                bv[np*2][0] = r[0]; bv[np*2][1] = r[1];
                bv[np*2+1][0] = r[2]; bv[np*2+1][1] = r[3];
            }
            #pragma unroll
            for (int mt = 0; mt < 4; mt++)
                #pragma unroll
                for (int nt = 0; nt < 4; nt++)
                    mma16816(acc[mt][nt], av[mt], bv[nt]);
        }
    }

    #pragma unroll
    for (int mt = 0; mt < 4; mt++)
        #pragma unroll
        for (int nt = 0; nt < 4; nt++) {
            const int row = m0 + wm + mt * 16 + (lane >> 2);
            const int col = n0 + wn + nt * 8 + (lane & 3) * 2;
            const long long i0 = ((long long)e * NT + row) * ND + col;
            const long long i1 = i0 + 8LL * ND;
            *(float2*)&Out[i0] = make_float2(acc[mt][nt][0], acc[mt][nt][1]);
            *(float2*)&Out[i1] = make_float2(acc[mt][nt][2], acc[mt][nt][3]);
        }
}

// ---------------- launch ----------------
// Inputs: x [E,T,D] fp32, w1 [E,D,H], w2 [E,H,D], w3 [E,D,H]. Output [E,T,D] fp32.
extern "C" void kernel_launch(void* const* d_in, const int* in_sizes, int n_in,
                              void* d_out, int out_size)
{
    const float* x  = (const float*)d_in[0];
    const float* w1 = (const float*)d_in[1];
    const float* w2 = (const float*)d_in[2];
    const float* w3 = (const float*)d_in[3];
    float* out = (float*)d_out;

    cudaFuncSetAttribute(gemm13_fused, cudaFuncAttributeMaxDynamicSharedMemorySize, 98304);
    cudaFuncSetAttribute(gemm2_out,    cudaFuncAttributeMaxDynamicSharedMemorySize, 98304);

    void *x16, *w1p, *w3p, *w2p, *h16;
    cudaGetSymbolAddress(&x16, g_x16);
    cudaGetSymbolAddress(&w1p, g_w1);
    cudaGetSymbolAddress(&w3p, g_w3);
    cudaGetSymbolAddress(&w2p, g_w2);
    cudaGetSymbolAddress(&h16, g_h16);

    // 1) merged conversion of x, w1, w3 (w2 is converted inside gemm13's launch)
    const long long UX = (long long)NE * NT * ND / 8;
    const long long UW = (long long)NE * ND * NH / 8;
    const long long UTOT = UX + 2 * UW;                  // 20,971,520 units
    conv3_kernel<<<(int)(UTOT / 256), 256>>>((const float4*)x, (const float4*)w1,
                                             (const float4*)w3);

    // 2) gemm13 (+ w2 conversion plane at blockIdx.z == NE)
    gemm13_fused<<<dim3(NH / 64, NT / 128, NE + 1), 256, 98304>>>(
        (const __half*)x16, (const __half*)w1p, (const __half*)w3p, (__half*)h16,
        (const float4*)w2);

    // 3) out = h @ w2
    gemm2_out<<<dim3(ND / 128, NT / 128, NE), 256, 98304>>>(
        (const __half*)h16, (const __half*)w2p, out);
}